// round 2
// baseline (speedup 1.0000x reference)
#include <cuda_runtime.h>
#include <cuda_bf16.h>
#include <cstdint>
#include <cstddef>

// Problem constants
#define BB   64          // batch
#define TT   1024        // timesteps
#define DD   512         // input dim
#define HH   512         // hidden dim
#define GG   2048        // 4*H gate dim
#define CCTA 64          // persistent CTAs for recurrence
#define NHH  8           // hidden cols per CTA = HH/CCTA

// ---------------- device scratch (static allocations only) ----------------
__device__ float    g_xproj[(size_t)TT * GG * BB];  // [t][gatecol][b], 512MB
__device__ float    g_Wx[GG * DD];                  // packed, tf32-rounded
__device__ float    g_Wh[GG * HH];                  // packed, tf32-rounded
__device__ float    g_bsum[GG];                     // bx + bh
__device__ float    g_h[2][BB * HH];                // h ping-pong, [b][h]
__device__ unsigned g_bar;

// ---------------- helpers ----------------
__device__ __forceinline__ float tf32r(float x) {
    float y;
    asm("cvt.rna.tf32.f32 %0, %1;" : "=f"(y) : "f"(x));
    return y;
}

__device__ __forceinline__ void mma8(float* c,
                                     unsigned a0, unsigned a1, unsigned a2, unsigned a3,
                                     unsigned b0, unsigned b1) {
    asm volatile(
        "mma.sync.aligned.m16n8k8.row.col.f32.tf32.tf32.f32 "
        "{%0,%1,%2,%3},{%4,%5,%6,%7},{%8,%9},{%0,%1,%2,%3};\n"
        : "+f"(c[0]), "+f"(c[1]), "+f"(c[2]), "+f"(c[3])
        : "r"(a0), "r"(a1), "r"(a2), "r"(a3), "r"(b0), "r"(b1));
}

__device__ __forceinline__ void cp16(float* dst, const float* src) {
    unsigned s = (unsigned)__cvta_generic_to_shared(dst);
    asm volatile("cp.async.cg.shared.global [%0], [%1], 16;\n" :: "r"(s), "l"(src));
}
#define CP_COMMIT  asm volatile("cp.async.commit_group;\n" ::: "memory")
#define CP_WAIT(N) asm volatile("cp.async.wait_group %0;\n" :: "n"(N) : "memory")

__device__ __forceinline__ float sigmoidf_(float x) {
    return 1.0f / (1.0f + __expf(-x));
}

// ---------------- pack kernel: concat + tf32-round weights, sum biases ----------------
__global__ void pack_kernel(
    const float* __restrict__ Wxf, const float* __restrict__ Wxi,
    const float* __restrict__ Wxg, const float* __restrict__ Wxo,
    const float* __restrict__ Whf, const float* __restrict__ Whi,
    const float* __restrict__ Whg, const float* __restrict__ Who,
    const float* __restrict__ bxf, const float* __restrict__ bxi,
    const float* __restrict__ bxg, const float* __restrict__ bxo,
    const float* __restrict__ bhf, const float* __restrict__ bhi,
    const float* __restrict__ bhg, const float* __restrict__ bho) {
    int i = blockIdx.x * blockDim.x + threadIdx.x;
    const float* WX[4] = {Wxf, Wxi, Wxg, Wxo};
    const float* WH[4] = {Whf, Whi, Whg, Who};
    const float* BX[4] = {bxf, bxi, bxg, bxo};
    const float* BH[4] = {bhf, bhi, bhg, bho};
    const int WN = GG * DD;  // 1M
    if (i < WN) {
        int row = i >> 9, col = i & 511;
        int g = row >> 9, rr = row & 511;
        g_Wx[i] = tf32r(WX[g][rr * DD + col]);
    } else if (i < 2 * WN) {
        int j = i - WN;
        int row = j >> 9, col = j & 511;
        int g = row >> 9, rr = row & 511;
        g_Wh[j] = tf32r(WH[g][rr * HH + col]);
    } else if (i < 2 * WN + GG) {
        int j = i - 2 * WN;
        int g = j >> 9, rr = j & 511;
        g_bsum[j] = BX[g][rr] + BH[g][rr];
    }
}

// ---------------- init kernel: zero h buffers + barrier counter ----------------
__global__ void init_kernel() {
    int i = blockIdx.x * blockDim.x + threadIdx.x;
    if (i < 2 * BB * HH) ((float*)g_h)[i] = 0.0f;
    if (i == 0) g_bar = 0u;
}

// ---------------- phase 1: x_proj[t][gcol][b] = Wx @ x_t^T + bsum ----------------
// CTA tile: M=128 gate cols x N=64 batch, K=512 in chunks of 64. 256 threads (8 warps, 4x2).
#define XP_SMEM_FLOATS (2 * 128 * 68 + 2 * 64 * 68)

__global__ void __launch_bounds__(256, 2) xproj_kernel(const float* __restrict__ x) {
    extern __shared__ float sm[];
    float* sA = sm;                  // [2][128][68]
    float* sB = sm + 2 * 128 * 68;   // [2][64][68]
    const int t  = blockIdx.y;
    const int c0 = blockIdx.x * 128;
    const int tid = threadIdx.x;
    const int w = tid >> 5, lane = tid & 31;
    const int wm = w & 3, wn = w >> 2;
    const int lg = lane >> 2, lt = lane & 3;

    float acc[2][4][4];
#pragma unroll
    for (int i = 0; i < 2; i++)
#pragma unroll
        for (int j = 0; j < 4; j++)
#pragma unroll
            for (int k = 0; k < 4; k++) acc[i][j][k] = 0.0f;

    auto loadA = [&](int buf, int k0) {
        float* dst = sA + buf * (128 * 68);
#pragma unroll
        for (int j = 0; j < 8; j++) {
            int l = tid + 256 * j;
            int row = l >> 4, q = l & 15;
            cp16(dst + row * 68 + q * 4, g_Wx + (size_t)(c0 + row) * DD + k0 + q * 4);
        }
    };
    auto loadB = [&](int buf, int k0) {
        float* dst = sB + buf * (64 * 68);
#pragma unroll
        for (int j = 0; j < 4; j++) {
            int l = tid + 256 * j;
            int row = l >> 4, q = l & 15;
            cp16(dst + row * 68 + q * 4, x + ((size_t)row * TT + t) * DD + k0 + q * 4);
        }
    };

    loadA(0, 0); loadB(0, 0); CP_COMMIT;
    for (int ch = 0; ch < 8; ch++) {
        if (ch < 7) {
            loadA((ch + 1) & 1, (ch + 1) * 64);
            loadB((ch + 1) & 1, (ch + 1) * 64);
            CP_COMMIT;
            CP_WAIT(1);
        } else {
            CP_WAIT(0);
        }
        __syncthreads();
        const float* A  = sA + (ch & 1) * (128 * 68);
        const float* Bm = sB + (ch & 1) * (64 * 68);
#pragma unroll
        for (int kk = 0; kk < 64; kk += 8) {
            unsigned a[2][4];
            unsigned b[4][2];
#pragma unroll
            for (int am = 0; am < 2; am++) {
                const float* p = A + (wm * 32 + am * 16 + lg) * 68 + kk + lt;
                a[am][0] = __float_as_uint(p[0]);
                a[am][1] = __float_as_uint(p[8 * 68]);
                a[am][2] = __float_as_uint(p[4]);
                a[am][3] = __float_as_uint(p[8 * 68 + 4]);
            }
#pragma unroll
            for (int bn = 0; bn < 4; bn++) {
                const float* p = Bm + (wn * 32 + bn * 8 + lg) * 68 + kk + lt;
                b[bn][0] = __float_as_uint(tf32r(p[0]));
                b[bn][1] = __float_as_uint(tf32r(p[4]));
            }
#pragma unroll
            for (int am = 0; am < 2; am++)
#pragma unroll
                for (int bn = 0; bn < 4; bn++)
                    mma8(acc[am][bn], a[am][0], a[am][1], a[am][2], a[am][3],
                         b[bn][0], b[bn][1]);
        }
        __syncthreads();
    }

    // epilogue: add (bx+bh), store [t][gcol][b]
#pragma unroll
    for (int am = 0; am < 2; am++) {
#pragma unroll
        for (int rr = 0; rr < 2; rr++) {
            int gcol = c0 + wm * 32 + am * 16 + rr * 8 + lg;
            float bs = g_bsum[gcol];
#pragma unroll
            for (int bn = 0; bn < 4; bn++) {
                int b = wn * 32 + bn * 8 + 2 * lt;
                float2 v = make_float2(acc[am][bn][2 * rr + 0] + bs,
                                       acc[am][bn][2 * rr + 1] + bs);
                *(float2*)&g_xproj[((size_t)t * GG + gcol) * BB + b] = v;
            }
        }
    }
}

// ---------------- phase 2: persistent recurrent kernel ----------------
// 64 CTAs x 128 threads. CTA r owns hidden cols [r*8, r*8+8) -> 32 gate rows.
// smem: Wh slice [32][516], h staging [2][64][132], gate dump [32][68].
#define LSTM_SMEM_FLOATS (32 * 516 + 2 * 64 * 132 + 32 * 68)

__global__ void __launch_bounds__(128, 1) lstm_kernel(float* __restrict__ out) {
    extern __shared__ float sm[];
    float* sWh = sm;                        // [32][516]
    float* sH  = sm + 32 * 516;             // [2][64][132]
    float* sG  = sH + 2 * 64 * 132;         // [32][68]
    const int r = blockIdx.x;
    const int tid = threadIdx.x;
    const int w = tid >> 5, lane = tid & 31;
    const int wm = w & 1, wn = w >> 1;
    const int lg = lane >> 2, lt = lane & 3;

    // preload Wh slice (tf32-rounded already): local row gg*8+j <-> global row gg*512 + r*8 + j
    for (int i = tid; i < 32 * 128; i += 128) {
        int lr = i >> 7, q = i & 127;
        int gg = lr >> 3, j = lr & 7;
        const float4 v = *(const float4*)(g_Wh + (size_t)(gg * 512 + r * 8 + j) * HH + q * 4);
        *(float4*)(sWh + lr * 516 + q * 4) = v;
    }

    const int jp = tid & 7;         // hidden col within slice
    const int b0 = (tid >> 3) * 4;  // 4 batches per thread
    float cst[4] = {0.0f, 0.0f, 0.0f, 0.0f};
    __syncthreads();

    for (int t = 0; t < TT; t++) {
        const float* hsrc = g_h[t & 1];
        float*       hdst = g_h[(t & 1) ^ 1];

        // prefetch x_proj contributions for this thread's cells (includes both biases)
        float4 xp[4];
#pragma unroll
        for (int g = 0; g < 4; g++)
            xp[g] = *(const float4*)(g_xproj +
                     ((size_t)t * GG + (g * 512 + r * 8 + jp)) * BB + b0);

        auto loadH = [&](int buf, int k0) {
            float* dst = sH + buf * (64 * 132);
#pragma unroll
            for (int j2 = 0; j2 < 16; j2++) {
                int l = tid + 128 * j2;
                int row = l >> 5, q = l & 31;
                cp16(dst + row * 132 + q * 4, hsrc + (size_t)row * HH + k0 + q * 4);
            }
        };

        float acc[4][4];
#pragma unroll
        for (int i = 0; i < 4; i++)
#pragma unroll
            for (int j3 = 0; j3 < 4; j3++) acc[i][j3] = 0.0f;

        loadH(0, 0); CP_COMMIT;
#pragma unroll
        for (int ch = 0; ch < 4; ch++) {
            if (ch < 3) {
                loadH((ch + 1) & 1, (ch + 1) * 128);
                CP_COMMIT;
                CP_WAIT(1);
            } else {
                CP_WAIT(0);
            }
            __syncthreads();
            const float* Hc = sH + (ch & 1) * (64 * 132);
            const float* Arow = sWh + (wm * 16 + lg) * 516 + ch * 128 + lt;
#pragma unroll
            for (int kk = 0; kk < 128; kk += 8) {
                const float* pa = Arow + kk;
                unsigned a0 = __float_as_uint(pa[0]);
                unsigned a1 = __float_as_uint(pa[8 * 516]);
                unsigned a2 = __float_as_uint(pa[4]);
                unsigned a3 = __float_as_uint(pa[8 * 516 + 4]);
#pragma unroll
                for (int bn = 0; bn < 4; bn++) {
                    const float* pb = Hc + (wn * 32 + bn * 8 + lg) * 132 + kk + lt;
                    mma8(acc[bn], a0, a1, a2, a3,
                         __float_as_uint(pb[0]), __float_as_uint(pb[4]));
                }
            }
            __syncthreads();
        }

        // dump raw h-gates to smem
#pragma unroll
        for (int bn = 0; bn < 4; bn++) {
            int b = wn * 32 + bn * 8 + 2 * lt;
            *(float2*)&sG[(wm * 16 + lg) * 68 + b]     = make_float2(acc[bn][0], acc[bn][1]);
            *(float2*)&sG[(wm * 16 + 8 + lg) * 68 + b] = make_float2(acc[bn][2], acc[bn][3]);
        }
        __syncthreads();

        // cell update: each thread owns (jp, b0..b0+3)
        float4 fg  = *(float4*)&sG[(0 * 8 + jp) * 68 + b0];
        float4 ig  = *(float4*)&sG[(1 * 8 + jp) * 68 + b0];
        float4 gg4 = *(float4*)&sG[(2 * 8 + jp) * 68 + b0];
        float4 og  = *(float4*)&sG[(3 * 8 + jp) * 68 + b0];
        float fv[4] = {fg.x + xp[0].x, fg.y + xp[0].y, fg.z + xp[0].z, fg.w + xp[0].w};
        float iv[4] = {ig.x + xp[1].x, ig.y + xp[1].y, ig.z + xp[1].z, ig.w + xp[1].w};
        float gv[4] = {gg4.x + xp[2].x, gg4.y + xp[2].y, gg4.z + xp[2].z, gg4.w + xp[2].w};
        float ov[4] = {og.x + xp[3].x, og.y + xp[3].y, og.z + xp[3].z, og.w + xp[3].w};
#pragma unroll
        for (int k2 = 0; k2 < 4; k2++) {
            float f_ = sigmoidf_(fv[k2]);
            float i_ = sigmoidf_(iv[k2]);
            float g_ = tanhf(gv[k2]);
            float o_ = sigmoidf_(ov[k2]);
            cst[k2] = f_ * cst[k2] + i_ * g_;
            float h_ = o_ * tanhf(cst[k2]);
            hdst[(size_t)(b0 + k2) * HH + r * 8 + jp] = tf32r(h_);
            if (t == TT - 1) out[(size_t)(b0 + k2) * HH + r * 8 + jp] = h_;
        }

        // grid barrier (release/acquire), double-buffered h so one barrier/step suffices
        __threadfence();
        __syncthreads();
        if (tid == 0) {
            unsigned one = 1u;
            asm volatile("red.release.gpu.global.add.u32 [%0], %1;"
                         :: "l"(&g_bar), "r"(one) : "memory");
            unsigned target = (unsigned)(t + 1) * CCTA;
            unsigned v;
            do {
                asm volatile("ld.acquire.gpu.global.u32 %0, [%1];"
                             : "=r"(v) : "l"(&g_bar) : "memory");
            } while (v < target);
        }
        __syncthreads();
    }
}

// ---------------- launcher ----------------
extern "C" void kernel_launch(void* const* d_in, const int* in_sizes, int n_in,
                              void* d_out, int out_size) {
    const float* x   = (const float*)d_in[0];
    const float* Whf = (const float*)d_in[1];  const float* bhf = (const float*)d_in[2];
    const float* Wxf = (const float*)d_in[3];  const float* bxf = (const float*)d_in[4];
    const float* Whi = (const float*)d_in[5];  const float* bhi = (const float*)d_in[6];
    const float* Wxi = (const float*)d_in[7];  const float* bxi = (const float*)d_in[8];
    const float* Whg = (const float*)d_in[9];  const float* bhg = (const float*)d_in[10];
    const float* Wxg = (const float*)d_in[11]; const float* bxg = (const float*)d_in[12];
    const float* Who = (const float*)d_in[13]; const float* bho = (const float*)d_in[14];
    const float* Wxo = (const float*)d_in[15]; const float* bxo = (const float*)d_in[16];

    const int xp_smem   = XP_SMEM_FLOATS * 4;    // 104448 B
    const int lstm_smem = LSTM_SMEM_FLOATS * 4;  // 142336 B
    cudaFuncSetAttribute(xproj_kernel, cudaFuncAttributeMaxDynamicSharedMemorySize, xp_smem);
    cudaFuncSetAttribute(lstm_kernel,  cudaFuncAttributeMaxDynamicSharedMemorySize, lstm_smem);

    int packN = 2 * GG * DD + GG;
    pack_kernel<<<(packN + 255) / 256, 256>>>(Wxf, Wxi, Wxg, Wxo,
                                              Whf, Whi, Whg, Who,
                                              bxf, bxi, bxg, bxo,
                                              bhf, bhi, bhg, bho);
    init_kernel<<<(2 * BB * HH + 255) / 256, 256>>>();

    dim3 g1(GG / 128, TT);
    xproj_kernel<<<g1, 256, xp_smem>>>(x);

    lstm_kernel<<<CCTA, 128, lstm_smem>>>((float*)d_out);
}

// round 4
// speedup vs baseline: 1.1149x; 1.1149x over previous
#include <cuda_runtime.h>
#include <cuda_bf16.h>
#include <cstdint>
#include <cstddef>

// Problem constants
#define BB   64          // batch
#define TT   1024        // timesteps
#define DD   512         // input dim
#define HH   512         // hidden dim
#define GG   2048        // 4*H gate dim
#define CCTA 64          // persistent CTAs for recurrence

// ---------------- device scratch (static allocations only) ----------------
__device__ float    g_xproj[(size_t)TT * GG * BB];  // [t][gatecol][b]
__device__ float    g_Wx[GG * DD];                  // packed, tf32-rounded
__device__ float    g_Wh[GG * HH];                  // packed, tf32-rounded
__device__ float    g_bsum[GG];                     // bx + bh
__device__ float    g_h[2][BB * HH];                // h ping-pong, [b][h]
__device__ unsigned g_bar;

// ---------------- helpers ----------------
__device__ __forceinline__ float tf32r(float x) {
    float y;
    asm("cvt.rna.tf32.f32 %0, %1;" : "=f"(y) : "f"(x));
    return y;
}

__device__ __forceinline__ float tanh_fast(float x) {
    float y;
    asm("tanh.approx.f32 %0, %1;" : "=f"(y) : "f"(x));
    return y;
}
__device__ __forceinline__ float sig_fast(float x) {
    return fmaf(tanh_fast(0.5f * x), 0.5f, 0.5f);
}

__device__ __forceinline__ void mma8(float* c,
                                     unsigned a0, unsigned a1, unsigned a2, unsigned a3,
                                     unsigned b0, unsigned b1) {
    asm volatile(
        "mma.sync.aligned.m16n8k8.row.col.f32.tf32.tf32.f32 "
        "{%0,%1,%2,%3},{%4,%5,%6,%7},{%8,%9},{%0,%1,%2,%3};\n"
        : "+f"(c[0]), "+f"(c[1]), "+f"(c[2]), "+f"(c[3])
        : "r"(a0), "r"(a1), "r"(a2), "r"(a3), "r"(b0), "r"(b1));
}

__device__ __forceinline__ void cp16(float* dst, const float* src) {
    unsigned s = (unsigned)__cvta_generic_to_shared(dst);
    asm volatile("cp.async.cg.shared.global [%0], [%1], 16;\n" :: "r"(s), "l"(src));
}
#define CP_COMMIT  asm volatile("cp.async.commit_group;\n" ::: "memory")
#define CP_WAIT(N) asm volatile("cp.async.wait_group %0;\n" :: "n"(N) : "memory")

// ---------------- pack kernel ----------------
__global__ void pack_kernel(
    const float* __restrict__ Wxf, const float* __restrict__ Wxi,
    const float* __restrict__ Wxg, const float* __restrict__ Wxo,
    const float* __restrict__ Whf, const float* __restrict__ Whi,
    const float* __restrict__ Whg, const float* __restrict__ Who,
    const float* __restrict__ bxf, const float* __restrict__ bxi,
    const float* __restrict__ bxg, const float* __restrict__ bxo,
    const float* __restrict__ bhf, const float* __restrict__ bhi,
    const float* __restrict__ bhg, const float* __restrict__ bho) {
    int i = blockIdx.x * blockDim.x + threadIdx.x;
    const float* WX[4] = {Wxf, Wxi, Wxg, Wxo};
    const float* WH[4] = {Whf, Whi, Whg, Who};
    const float* BX[4] = {bxf, bxi, bxg, bxo};
    const float* BH[4] = {bhf, bhi, bhg, bho};
    const int WN = GG * DD;
    if (i < WN) {
        int row = i >> 9, col = i & 511;
        int g = row >> 9, rr = row & 511;
        g_Wx[i] = tf32r(WX[g][rr * DD + col]);
    } else if (i < 2 * WN) {
        int j = i - WN;
        int row = j >> 9, col = j & 511;
        int g = row >> 9, rr = row & 511;
        g_Wh[j] = tf32r(WH[g][rr * HH + col]);
    } else if (i < 2 * WN + GG) {
        int j = i - 2 * WN;
        int g = j >> 9, rr = j & 511;
        g_bsum[j] = BX[g][rr] + BH[g][rr];
    }
}

__global__ void init_kernel() {
    int i = blockIdx.x * blockDim.x + threadIdx.x;
    if (i < 2 * BB * HH) ((float*)g_h)[i] = 0.0f;
    if (i == 0) g_bar = 0u;
}

// ---------------- phase 1: x_proj (unchanged from R2) ----------------
#define XP_SMEM_FLOATS (2 * 128 * 68 + 2 * 64 * 68)

__global__ void __launch_bounds__(256, 2) xproj_kernel(const float* __restrict__ x) {
    extern __shared__ float sm[];
    float* sA = sm;
    float* sB = sm + 2 * 128 * 68;
    const int t  = blockIdx.y;
    const int c0 = blockIdx.x * 128;
    const int tid = threadIdx.x;
    const int w = tid >> 5, lane = tid & 31;
    const int wm = w & 3, wn = w >> 2;
    const int lg = lane >> 2, lt = lane & 3;

    float acc[2][4][4];
#pragma unroll
    for (int i = 0; i < 2; i++)
#pragma unroll
        for (int j = 0; j < 4; j++)
#pragma unroll
            for (int k = 0; k < 4; k++) acc[i][j][k] = 0.0f;

    auto loadA = [&](int buf, int k0) {
        float* dst = sA + buf * (128 * 68);
#pragma unroll
        for (int j = 0; j < 8; j++) {
            int l = tid + 256 * j;
            int row = l >> 4, q = l & 15;
            cp16(dst + row * 68 + q * 4, g_Wx + (size_t)(c0 + row) * DD + k0 + q * 4);
        }
    };
    auto loadB = [&](int buf, int k0) {
        float* dst = sB + buf * (64 * 68);
#pragma unroll
        for (int j = 0; j < 4; j++) {
            int l = tid + 256 * j;
            int row = l >> 4, q = l & 15;
            cp16(dst + row * 68 + q * 4, x + ((size_t)row * TT + t) * DD + k0 + q * 4);
        }
    };

    loadA(0, 0); loadB(0, 0); CP_COMMIT;
    for (int ch = 0; ch < 8; ch++) {
        if (ch < 7) {
            loadA((ch + 1) & 1, (ch + 1) * 64);
            loadB((ch + 1) & 1, (ch + 1) * 64);
            CP_COMMIT;
            CP_WAIT(1);
        } else {
            CP_WAIT(0);
        }
        __syncthreads();
        const float* A  = sA + (ch & 1) * (128 * 68);
        const float* Bm = sB + (ch & 1) * (64 * 68);
#pragma unroll
        for (int kk = 0; kk < 64; kk += 8) {
            unsigned a[2][4];
            unsigned b[4][2];
#pragma unroll
            for (int am = 0; am < 2; am++) {
                const float* p = A + (wm * 32 + am * 16 + lg) * 68 + kk + lt;
                a[am][0] = __float_as_uint(p[0]);
                a[am][1] = __float_as_uint(p[8 * 68]);
                a[am][2] = __float_as_uint(p[4]);
                a[am][3] = __float_as_uint(p[8 * 68 + 4]);
            }
#pragma unroll
            for (int bn = 0; bn < 4; bn++) {
                const float* p = Bm + (wn * 32 + bn * 8 + lg) * 68 + kk + lt;
                b[bn][0] = __float_as_uint(tf32r(p[0]));
                b[bn][1] = __float_as_uint(tf32r(p[4]));
            }
#pragma unroll
            for (int am = 0; am < 2; am++)
#pragma unroll
                for (int bn = 0; bn < 4; bn++)
                    mma8(acc[am][bn], a[am][0], a[am][1], a[am][2], a[am][3],
                         b[bn][0], b[bn][1]);
        }
        __syncthreads();
    }

#pragma unroll
    for (int am = 0; am < 2; am++) {
#pragma unroll
        for (int rr = 0; rr < 2; rr++) {
            int gcol = c0 + wm * 32 + am * 16 + rr * 8 + lg;
            float bs = g_bsum[gcol];
#pragma unroll
            for (int bn = 0; bn < 4; bn++) {
                int b = wn * 32 + bn * 8 + 2 * lt;
                float2 v = make_float2(acc[am][bn][2 * rr + 0] + bs,
                                       acc[am][bn][2 * rr + 1] + bs);
                *(float2*)&g_xproj[((size_t)t * GG + gcol) * BB + b] = v;
            }
        }
    }
}

// ---------------- phase 2: persistent recurrent kernel (rewritten) ----------------
// 64 CTAs x 256 threads. CTA r owns hidden cols [r*8, r*8+8) -> 32 gate rows
// (local row lr = g*8 + j  <->  global gate row g*512 + r*8 + j).
// smem: sWhp pre-swizzled A fragments [2 mt][64 q][32 lane] float4 = 64KB
//       sH full h [64][516] = 132KB,  sG [32][68] = 8.5KB
#define LSTM_SMEM_BYTES ((2 * 64 * 32 * 4 + 64 * 516 + 32 * 68) * 4)

__global__ void __launch_bounds__(256, 1) lstm_kernel(float* __restrict__ out) {
    extern __shared__ float sm[];
    float4* sWhp = (float4*)sm;               // 4096 float4
    float*  sH   = sm + 2 * 64 * 32 * 4;      // [64][516]
    float*  sG   = sH + 64 * 516;             // [32][68]
    const int r = blockIdx.x;
    const int tid = threadIdx.x;
    const int w = tid >> 5, lane = tid & 31;
    const int wm = w & 1;        // m-tile (16 gate rows)
    const int wn = w >> 1;       // n-tile (16 batches), 0..3
    const int lg = lane >> 2, lt = lane & 3;

    // ---- preload Wh slice, pre-swizzled into mma-A fragment order ----
    for (int i = tid; i < 2 * 64 * 32; i += 256) {
        int mt = i >> 11;
        int rem = i & 2047;
        int q = rem >> 5, ln = rem & 31;
        int flg = ln >> 2, flt = ln & 3;
        int lr0 = mt * 16 + flg, lr1 = lr0 + 8;
        int c0 = q * 8 + flt, c1 = c0 + 4;
        int gr0 = ((lr0 >> 3) << 9) + r * 8 + (lr0 & 7);  // global gate row
        int gr1 = ((lr1 >> 3) << 9) + r * 8 + (lr1 & 7);
        float4 v;
        v.x = g_Wh[(size_t)gr0 * HH + c0];
        v.y = g_Wh[(size_t)gr1 * HH + c0];
        v.z = g_Wh[(size_t)gr0 * HH + c1];
        v.w = g_Wh[(size_t)gr1 * HH + c1];
        sWhp[i] = v;
    }

    const int jp = tid & 7;            // hidden col within slice
    const int bb = (tid >> 3) * 2;     // 2 consecutive batches per thread
    float cst[2] = {0.0f, 0.0f};

    // x_proj prefetch lambda (includes both biases already)
    float2 xc[4], xn[4];
    auto ldxp = [&](int tt, float2* v) {
        const float* base = g_xproj + (size_t)tt * GG * BB;
#pragma unroll
        for (int g = 0; g < 4; g++)
            v[g] = *(const float2*)(base + (size_t)(g * 512 + r * 8 + jp) * BB + bb);
    };
    ldxp(0, xc);
    __syncthreads();

    const float4* aP = sWhp + wm * 2048 + lane;
    const float* bP0 = sH + (wn * 16 + lg) * 516 + lt;
    const float* bP1 = sH + (wn * 16 + 8 + lg) * 516 + lt;

    for (int t = 0; t < TT; t++) {
        const float* hsrc = g_h[t & 1];
        float*       hdst = g_h[(t & 1) ^ 1];

        // stage full h (64x512 f32) in two commit groups (K halves)
#pragma unroll
        for (int c = 0; c < 2; c++) {
#pragma unroll
            for (int j = 0; j < 16; j++) {
                int l = tid + 256 * j;
                int row = l >> 6, q = l & 63;
                cp16(sH + row * 516 + c * 256 + q * 4,
                     hsrc + (size_t)row * HH + c * 256 + q * 4);
            }
            CP_COMMIT;
        }
        // prefetch next step's x_proj during the MMA
        if (t + 1 < TT) ldxp(t + 1, xn);

        float acc0[4] = {0, 0, 0, 0}, acc1[4] = {0, 0, 0, 0};

        CP_WAIT(1);
        __syncthreads();
#pragma unroll 8
        for (int q = 0; q < 32; q++) {
            float4 av = aP[q * 32];
            unsigned b00 = __float_as_uint(bP0[q * 8]);
            unsigned b01 = __float_as_uint(bP0[q * 8 + 4]);
            unsigned b10 = __float_as_uint(bP1[q * 8]);
            unsigned b11 = __float_as_uint(bP1[q * 8 + 4]);
            mma8(acc0, __float_as_uint(av.x), __float_as_uint(av.y),
                       __float_as_uint(av.z), __float_as_uint(av.w), b00, b01);
            mma8(acc1, __float_as_uint(av.x), __float_as_uint(av.y),
                       __float_as_uint(av.z), __float_as_uint(av.w), b10, b11);
        }
        CP_WAIT(0);
        __syncthreads();
#pragma unroll 8
        for (int q = 32; q < 64; q++) {
            float4 av = aP[q * 32];
            unsigned b00 = __float_as_uint(bP0[q * 8]);
            unsigned b01 = __float_as_uint(bP0[q * 8 + 4]);
            unsigned b10 = __float_as_uint(bP1[q * 8]);
            unsigned b11 = __float_as_uint(bP1[q * 8 + 4]);
            mma8(acc0, __float_as_uint(av.x), __float_as_uint(av.y),
                       __float_as_uint(av.z), __float_as_uint(av.w), b00, b01);
            mma8(acc1, __float_as_uint(av.x), __float_as_uint(av.y),
                       __float_as_uint(av.z), __float_as_uint(av.w), b10, b11);
        }

        // dump raw h-gates to sG[32 gate rows][64 batches]
        {
            int rr0 = wm * 16 + lg, rr1 = rr0 + 8;
            int n0 = wn * 16 + 2 * lt;
            *(float2*)&sG[rr0 * 68 + n0]     = make_float2(acc0[0], acc0[1]);
            *(float2*)&sG[rr1 * 68 + n0]     = make_float2(acc0[2], acc0[3]);
            *(float2*)&sG[rr0 * 68 + n0 + 8] = make_float2(acc1[0], acc1[1]);
            *(float2*)&sG[rr1 * 68 + n0 + 8] = make_float2(acc1[2], acc1[3]);
        }
        __syncthreads();

        // cell update: thread owns (jp, bb..bb+1)
        float2 f2 = *(float2*)&sG[(0 * 8 + jp) * 68 + bb];
        float2 i2 = *(float2*)&sG[(1 * 8 + jp) * 68 + bb];
        float2 g2 = *(float2*)&sG[(2 * 8 + jp) * 68 + bb];
        float2 o2 = *(float2*)&sG[(3 * 8 + jp) * 68 + bb];
        float fv[2] = {f2.x + xc[0].x, f2.y + xc[0].y};
        float iv[2] = {i2.x + xc[1].x, i2.y + xc[1].y};
        float gv[2] = {g2.x + xc[2].x, g2.y + xc[2].y};
        float ov[2] = {o2.x + xc[3].x, o2.y + xc[3].y};
#pragma unroll
        for (int k = 0; k < 2; k++) {
            float f_ = sig_fast(fv[k]);
            float i_ = sig_fast(iv[k]);
            float g_ = tanh_fast(gv[k]);
            float o_ = sig_fast(ov[k]);
            cst[k] = f_ * cst[k] + i_ * g_;
            float h_ = o_ * tanh_fast(cst[k]);
            hdst[(size_t)(bb + k) * HH + r * 8 + jp] = tf32r(h_);
            if (t == TT - 1) out[(size_t)(bb + k) * HH + r * 8 + jp] = h_;
        }
#pragma unroll
        for (int g = 0; g < 4; g++) xc[g] = xn[g];

        // grid barrier: syncthreads + cumulative release-add, acquire-poll
        __syncthreads();
        if (tid == 0) {
            unsigned one = 1u;
            asm volatile("red.release.gpu.global.add.u32 [%0], %1;"
                         :: "l"(&g_bar), "r"(one) : "memory");
            unsigned target = (unsigned)(t + 1) * CCTA;
            unsigned v;
            do {
                asm volatile("ld.acquire.gpu.global.u32 %0, [%1];"
                             : "=r"(v) : "l"(&g_bar) : "memory");
            } while (v < target);
        }
        __syncthreads();
    }
}

// ---------------- launcher ----------------
extern "C" void kernel_launch(void* const* d_in, const int* in_sizes, int n_in,
                              void* d_out, int out_size) {
    const float* x   = (const float*)d_in[0];
    const float* Whf = (const float*)d_in[1];  const float* bhf = (const float*)d_in[2];
    const float* Wxf = (const float*)d_in[3];  const float* bxf = (const float*)d_in[4];
    const float* Whi = (const float*)d_in[5];  const float* bhi = (const float*)d_in[6];
    const float* Wxi = (const float*)d_in[7];  const float* bxi = (const float*)d_in[8];
    const float* Whg = (const float*)d_in[9];  const float* bhg = (const float*)d_in[10];
    const float* Wxg = (const float*)d_in[11]; const float* bxg = (const float*)d_in[12];
    const float* Who = (const float*)d_in[13]; const float* bho = (const float*)d_in[14];
    const float* Wxo = (const float*)d_in[15]; const float* bxo = (const float*)d_in[16];

    const int xp_smem   = XP_SMEM_FLOATS * 4;
    const int lstm_smem = LSTM_SMEM_BYTES;
    cudaFuncSetAttribute(xproj_kernel, cudaFuncAttributeMaxDynamicSharedMemorySize, xp_smem);
    cudaFuncSetAttribute(lstm_kernel,  cudaFuncAttributeMaxDynamicSharedMemorySize, lstm_smem);

    int packN = 2 * GG * DD + GG;
    pack_kernel<<<(packN + 255) / 256, 256>>>(Wxf, Wxi, Wxg, Wxo,
                                              Whf, Whi, Whg, Who,
                                              bxf, bxi, bxg, bxo,
                                              bhf, bhi, bhg, bho);
    init_kernel<<<(2 * BB * HH + 255) / 256, 256>>>();

    dim3 g1(GG / 128, TT);
    xproj_kernel<<<g1, 256, xp_smem>>>(x);

    lstm_kernel<<<CCTA, 256, lstm_smem>>>((float*)d_out);
}

// round 5
// speedup vs baseline: 1.6520x; 1.4817x over previous
#include <cuda_runtime.h>
#include <cuda_bf16.h>
#include <cstdint>
#include <cstddef>

// Problem constants
#define BB   64          // batch
#define TT   1024        // timesteps
#define DD   512         // input dim
#define HH   512         // hidden dim
#define GG   2048        // 4*H gate dim
#define NGRP 4           // independent batch groups
#define GCTA 32          // CTAs per group
#define NB   16          // batches per group
#define NCOL 16          // hidden cols per CTA

// ---------------- device scratch ----------------
__device__ float    g_xproj[(size_t)TT * GG * BB];  // [t][gcol][b]
__device__ float    g_Wx[GG * DD];
__device__ float    g_Wh[GG * HH];
__device__ float    g_bsum[GG];
__device__ float    g_h[2][NGRP * NB * HH];         // per-group h, k-PERMUTED cols
__device__ unsigned g_bar4[NGRP * 32];              // padded barrier counters

// ---------------- helpers ----------------
__device__ __forceinline__ float tf32r(float x) {
    float y; asm("cvt.rna.tf32.f32 %0, %1;" : "=f"(y) : "f"(x)); return y;
}
__device__ __forceinline__ float tanh_fast(float x) {
    float y; asm("tanh.approx.f32 %0, %1;" : "=f"(y) : "f"(x)); return y;
}
__device__ __forceinline__ float sig_fast(float x) {
    return fmaf(tanh_fast(0.5f * x), 0.5f, 0.5f);
}
__device__ __forceinline__ void mma8(float* c,
                                     unsigned a0, unsigned a1, unsigned a2, unsigned a3,
                                     unsigned b0, unsigned b1) {
    asm volatile(
        "mma.sync.aligned.m16n8k8.row.col.f32.tf32.tf32.f32 "
        "{%0,%1,%2,%3},{%4,%5,%6,%7},{%8,%9},{%0,%1,%2,%3};\n"
        : "+f"(c[0]), "+f"(c[1]), "+f"(c[2]), "+f"(c[3])
        : "r"(a0), "r"(a1), "r"(a2), "r"(a3), "r"(b0), "r"(b1));
}
__device__ __forceinline__ void cp16(float* dst, const float* src) {
    unsigned s = (unsigned)__cvta_generic_to_shared(dst);
    asm volatile("cp.async.cg.shared.global [%0], [%1], 16;\n" :: "r"(s), "l"(src));
}
#define CP_COMMIT  asm volatile("cp.async.commit_group;\n" ::: "memory")
#define CP_WAIT(N) asm volatile("cp.async.wait_group %0;\n" :: "n"(N) : "memory")

// k-permutation within each 8-block: true offset o -> stored offset
__device__ __host__ __forceinline__ int kperm(int o) {
    return (o < 4) ? 2 * o : 2 * (o - 4) + 1;
}

// ---------------- pack kernel ----------------
__global__ void pack_kernel(
    const float* __restrict__ Wxf, const float* __restrict__ Wxi,
    const float* __restrict__ Wxg, const float* __restrict__ Wxo,
    const float* __restrict__ Whf, const float* __restrict__ Whi,
    const float* __restrict__ Whg, const float* __restrict__ Who,
    const float* __restrict__ bxf, const float* __restrict__ bxi,
    const float* __restrict__ bxg, const float* __restrict__ bxo,
    const float* __restrict__ bhf, const float* __restrict__ bhi,
    const float* __restrict__ bhg, const float* __restrict__ bho) {
    int i = blockIdx.x * blockDim.x + threadIdx.x;
    const float* WX[4] = {Wxf, Wxi, Wxg, Wxo};
    const float* WH[4] = {Whf, Whi, Whg, Who};
    const float* BX[4] = {bxf, bxi, bxg, bxo};
    const float* BH[4] = {bhf, bhi, bhg, bho};
    const int WN = GG * DD;
    if (i < WN) {
        int row = i >> 9, col = i & 511;
        int g = row >> 9, rr = row & 511;
        g_Wx[i] = tf32r(WX[g][rr * DD + col]);
    } else if (i < 2 * WN) {
        int j = i - WN;
        int row = j >> 9, col = j & 511;
        int g = row >> 9, rr = row & 511;
        g_Wh[j] = tf32r(WH[g][rr * HH + col]);
    } else if (i < 2 * WN + GG) {
        int j = i - 2 * WN;
        int g = j >> 9, rr = j & 511;
        g_bsum[j] = BX[g][rr] + BH[g][rr];
    }
}

__global__ void init_kernel() {
    int i = blockIdx.x * blockDim.x + threadIdx.x;
    if (i < 2 * NGRP * NB * HH) ((float*)g_h)[i] = 0.0f;
    if (i < NGRP * 32) g_bar4[i] = 0u;
}

// ---------------- phase 1: x_proj (unchanged) ----------------
#define XP_SMEM_FLOATS (2 * 128 * 68 + 2 * 64 * 68)

__global__ void __launch_bounds__(256, 2) xproj_kernel(const float* __restrict__ x) {
    extern __shared__ float sm[];
    float* sA = sm;
    float* sB = sm + 2 * 128 * 68;
    const int t  = blockIdx.y;
    const int c0 = blockIdx.x * 128;
    const int tid = threadIdx.x;
    const int w = tid >> 5, lane = tid & 31;
    const int wm = w & 3, wn = w >> 2;
    const int lg = lane >> 2, lt = lane & 3;

    float acc[2][4][4];
#pragma unroll
    for (int i = 0; i < 2; i++)
#pragma unroll
        for (int j = 0; j < 4; j++)
#pragma unroll
            for (int k = 0; k < 4; k++) acc[i][j][k] = 0.0f;

    auto loadA = [&](int buf, int k0) {
        float* dst = sA + buf * (128 * 68);
#pragma unroll
        for (int j = 0; j < 8; j++) {
            int l = tid + 256 * j;
            int row = l >> 4, q = l & 15;
            cp16(dst + row * 68 + q * 4, g_Wx + (size_t)(c0 + row) * DD + k0 + q * 4);
        }
    };
    auto loadB = [&](int buf, int k0) {
        float* dst = sB + buf * (64 * 68);
#pragma unroll
        for (int j = 0; j < 4; j++) {
            int l = tid + 256 * j;
            int row = l >> 4, q = l & 15;
            cp16(dst + row * 68 + q * 4, x + ((size_t)row * TT + t) * DD + k0 + q * 4);
        }
    };

    loadA(0, 0); loadB(0, 0); CP_COMMIT;
    for (int ch = 0; ch < 8; ch++) {
        if (ch < 7) {
            loadA((ch + 1) & 1, (ch + 1) * 64);
            loadB((ch + 1) & 1, (ch + 1) * 64);
            CP_COMMIT;
            CP_WAIT(1);
        } else {
            CP_WAIT(0);
        }
        __syncthreads();
        const float* A  = sA + (ch & 1) * (128 * 68);
        const float* Bm = sB + (ch & 1) * (64 * 68);
#pragma unroll
        for (int kk = 0; kk < 64; kk += 8) {
            unsigned a[2][4];
            unsigned b[4][2];
#pragma unroll
            for (int am = 0; am < 2; am++) {
                const float* p = A + (wm * 32 + am * 16 + lg) * 68 + kk + lt;
                a[am][0] = __float_as_uint(p[0]);
                a[am][1] = __float_as_uint(p[8 * 68]);
                a[am][2] = __float_as_uint(p[4]);
                a[am][3] = __float_as_uint(p[8 * 68 + 4]);
            }
#pragma unroll
            for (int bn = 0; bn < 4; bn++) {
                const float* p = Bm + (wn * 32 + bn * 8 + lg) * 68 + kk + lt;
                b[bn][0] = __float_as_uint(tf32r(p[0]));
                b[bn][1] = __float_as_uint(tf32r(p[4]));
            }
#pragma unroll
            for (int am = 0; am < 2; am++)
#pragma unroll
                for (int bn = 0; bn < 4; bn++)
                    mma8(acc[am][bn], a[am][0], a[am][1], a[am][2], a[am][3],
                         b[bn][0], b[bn][1]);
        }
        __syncthreads();
    }

#pragma unroll
    for (int am = 0; am < 2; am++) {
#pragma unroll
        for (int rr = 0; rr < 2; rr++) {
            int gcol = c0 + wm * 32 + am * 16 + rr * 8 + lg;
            float bs = g_bsum[gcol];
#pragma unroll
            for (int bn = 0; bn < 4; bn++) {
                int b = wn * 32 + bn * 8 + 2 * lt;
                float2 v = make_float2(acc[am][bn][2 * rr + 0] + bs,
                                       acc[am][bn][2 * rr + 1] + bs);
                *(float2*)&g_xproj[((size_t)t * GG + gcol) * BB + b] = v;
            }
        }
    }
}

// ---------------- phase 2: persistent recurrent kernel ----------------
// 128 CTAs x 256 threads. group = bid>>5 (16 batches), r = bid&31 (16 hidden cols).
// Per CTA: M = 64 gate rows (4 gate-tiles x 16 cols), N = 16 batches, K = 512.
// Warps 0,1 do mma: warp wm covers gate-tiles {2wm, 2wm+1} (m32 x n16),
// K interleaved-split into 2 acc sets (depth 32 chains).
// smem: sWhp A-frags [4 gt][64 q][32 lane] float4 = 128KB
//       sH [16][520] = 33.3KB (k-permuted cols),  sG [4*16][18] = 4.6KB
#define SWHP_F4   (4 * 64 * 32)
#define SH_STRIDE 520
#define SG_STRIDE 18
#define LSTM_SMEM_BYTES ((SWHP_F4 * 4 + NB * SH_STRIDE + 64 * SG_STRIDE) * 4)

__global__ void __launch_bounds__(256, 1) lstm_kernel(float* __restrict__ out) {
    extern __shared__ float sm[];
    float4* sWhp = (float4*)sm;                       // A fragments
    float*  sH   = sm + SWHP_F4 * 4;                  // [16][520]
    float*  sG   = sH + NB * SH_STRIDE;               // [64][18]
    const int group = blockIdx.x >> 5;
    const int r     = blockIdx.x & 31;
    const int tid = threadIdx.x;
    const int w = tid >> 5, lane = tid & 31;
    const int lg = lane >> 2, lt = lane & 3;

    // ---- build pre-swizzled A fragments from g_Wh ----
    for (int i = tid; i < SWHP_F4; i += 256) {
        int gt = i >> 11;
        int rem = i & 2047;
        int q = rem >> 5, ln = rem & 31;
        int flg = ln >> 2, flt = ln & 3;
        int row0 = gt * 512 + r * NCOL + flg;       // global gate row (col flg)
        int row1 = row0 + 8;                         // col flg+8
        int c0 = q * 8 + flt, c1 = c0 + 4;           // true k cols
        float4 v;
        v.x = g_Wh[(size_t)row0 * HH + c0];
        v.y = g_Wh[(size_t)row1 * HH + c0];
        v.z = g_Wh[(size_t)row0 * HH + c1];
        v.w = g_Wh[(size_t)row1 * HH + c1];
        sWhp[i] = v;
    }

    // cell-update ownership: 1 cell per thread
    const int jl = tid >> 4;          // local hidden col 0..15
    const int bl = tid & 15;          // local batch 0..15
    const int jglob = r * NCOL + jl;
    const int bglob = group * NB + bl;
    const int pj = (jglob & ~7) | kperm(jglob & 7);  // permuted h position
    float cst = 0.0f;

    float4 xc, xn;  // f,i,g,o xproj for my cell
    auto ldxp = [&](int tt) {
        const float* base = g_xproj + (size_t)tt * GG * BB;
        float4 v;
        v.x = base[(size_t)(0 * 512 + jglob) * BB + bglob];
        v.y = base[(size_t)(1 * 512 + jglob) * BB + bglob];
        v.z = base[(size_t)(2 * 512 + jglob) * BB + bglob];
        v.w = base[(size_t)(3 * 512 + jglob) * BB + bglob];
        return v;
    };
    xc = ldxp(0);
    __syncthreads();

    const int wm = w;  // mma warps: w = 0,1
    const float4* aP0 = sWhp + (2 * wm + 0) * 2048 + lane;
    const float4* aP1 = sWhp + (2 * wm + 1) * 2048 + lane;
    const float* bP0 = sH + (0 * 8 + lg) * SH_STRIDE + 2 * lt;
    const float* bP1 = sH + (1 * 8 + lg) * SH_STRIDE + 2 * lt;
    unsigned* mybar = &g_bar4[group * 32];

    for (int t = 0; t < TT; t++) {
        const float* hsrc = g_h[t & 1] + (size_t)group * NB * HH;
        float*       hdst = g_h[(t & 1) ^ 1] + (size_t)group * NB * HH;

        // stage h (16 x 512 f32, k-permuted layout preserved)
#pragma unroll
        for (int j = 0; j < 8; j++) {
            int l = tid + 256 * j;
            int row = l >> 7, q = l & 127;
            cp16(sH + row * SH_STRIDE + q * 4, hsrc + (size_t)row * HH + q * 4);
        }
        CP_COMMIT;

        if (t + 1 < TT) xn = ldxp(t + 1);

        CP_WAIT(0);
        __syncthreads();

        if (w < 2) {
            // acc[h][i][nt][4]: h = K-half, i = gate-tile within pair, nt = n-tile
            float acc[2][2][2][4];
#pragma unroll
            for (int a = 0; a < 2; a++)
#pragma unroll
                for (int b = 0; b < 2; b++)
#pragma unroll
                    for (int c = 0; c < 2; c++)
#pragma unroll
                        for (int d = 0; d < 4; d++) acc[a][b][c][d] = 0.0f;

#pragma unroll 4
            for (int q = 0; q < 32; q++) {
#pragma unroll
                for (int h = 0; h < 2; h++) {
                    int kq = q + 32 * h;
                    float4 a0 = aP0[kq * 32];
                    float4 a1 = aP1[kq * 32];
                    float2 b0 = *(const float2*)(bP0 + kq * 8);
                    float2 b1 = *(const float2*)(bP1 + kq * 8);
                    unsigned ub00 = __float_as_uint(b0.x), ub01 = __float_as_uint(b0.y);
                    unsigned ub10 = __float_as_uint(b1.x), ub11 = __float_as_uint(b1.y);
                    mma8(acc[h][0][0], __float_as_uint(a0.x), __float_as_uint(a0.y),
                         __float_as_uint(a0.z), __float_as_uint(a0.w), ub00, ub01);
                    mma8(acc[h][0][1], __float_as_uint(a0.x), __float_as_uint(a0.y),
                         __float_as_uint(a0.z), __float_as_uint(a0.w), ub10, ub11);
                    mma8(acc[h][1][0], __float_as_uint(a1.x), __float_as_uint(a1.y),
                         __float_as_uint(a1.z), __float_as_uint(a1.w), ub00, ub01);
                    mma8(acc[h][1][1], __float_as_uint(a1.x), __float_as_uint(a1.y),
                         __float_as_uint(a1.z), __float_as_uint(a1.w), ub10, ub11);
                }
            }

            // merge K-halves and dump gates to sG[gate*16+col][batch]
#pragma unroll
            for (int i = 0; i < 2; i++) {
                int gate = 2 * wm + i;
#pragma unroll
                for (int nt = 0; nt < 2; nt++) {
                    int nb0 = nt * 8 + 2 * lt;
                    float v0 = acc[0][i][nt][0] + acc[1][i][nt][0];
                    float v1 = acc[0][i][nt][1] + acc[1][i][nt][1];
                    float v2 = acc[0][i][nt][2] + acc[1][i][nt][2];
                    float v3 = acc[0][i][nt][3] + acc[1][i][nt][3];
                    *(float2*)&sG[(gate * 16 + lg) * SG_STRIDE + nb0]     = make_float2(v0, v1);
                    *(float2*)&sG[(gate * 16 + lg + 8) * SG_STRIDE + nb0] = make_float2(v2, v3);
                }
            }
        }
        __syncthreads();

        // cell update (1 cell per thread)
        {
            float fv = sG[(0 * 16 + jl) * SG_STRIDE + bl] + xc.x;
            float iv = sG[(1 * 16 + jl) * SG_STRIDE + bl] + xc.y;
            float gv = sG[(2 * 16 + jl) * SG_STRIDE + bl] + xc.z;
            float ov = sG[(3 * 16 + jl) * SG_STRIDE + bl] + xc.w;
            float f_ = sig_fast(fv);
            float i_ = sig_fast(iv);
            float g_ = tanh_fast(gv);
            float o_ = sig_fast(ov);
            cst = f_ * cst + i_ * g_;
            float h_ = o_ * tanh_fast(cst);
            hdst[(size_t)bl * HH + pj] = tf32r(h_);
            if (t == TT - 1) out[(size_t)bglob * HH + jglob] = h_;
            xc = xn;
        }

        // group barrier
        __syncthreads();
        if (tid == 0) {
            unsigned one = 1u;
            asm volatile("red.release.gpu.global.add.u32 [%0], %1;"
                         :: "l"(mybar), "r"(one) : "memory");
            unsigned target = (unsigned)(t + 1) * GCTA;
            unsigned v;
            do {
                asm volatile("ld.acquire.gpu.global.u32 %0, [%1];"
                             : "=r"(v) : "l"(mybar) : "memory");
            } while (v < target);
        }
        __syncthreads();
    }
}

// ---------------- launcher ----------------
extern "C" void kernel_launch(void* const* d_in, const int* in_sizes, int n_in,
                              void* d_out, int out_size) {
    const float* x   = (const float*)d_in[0];
    const float* Whf = (const float*)d_in[1];  const float* bhf = (const float*)d_in[2];
    const float* Wxf = (const float*)d_in[3];  const float* bxf = (const float*)d_in[4];
    const float* Whi = (const float*)d_in[5];  const float* bhi = (const float*)d_in[6];
    const float* Wxi = (const float*)d_in[7];  const float* bxi = (const float*)d_in[8];
    const float* Whg = (const float*)d_in[9];  const float* bhg = (const float*)d_in[10];
    const float* Wxg = (const float*)d_in[11]; const float* bxg = (const float*)d_in[12];
    const float* Who = (const float*)d_in[13]; const float* bho = (const float*)d_in[14];
    const float* Wxo = (const float*)d_in[15]; const float* bxo = (const float*)d_in[16];

    const int xp_smem   = XP_SMEM_FLOATS * 4;
    const int lstm_smem = LSTM_SMEM_BYTES;
    cudaFuncSetAttribute(xproj_kernel, cudaFuncAttributeMaxDynamicSharedMemorySize, xp_smem);
    cudaFuncSetAttribute(lstm_kernel,  cudaFuncAttributeMaxDynamicSharedMemorySize, lstm_smem);

    int packN = 2 * GG * DD + GG;
    pack_kernel<<<(packN + 255) / 256, 256>>>(Wxf, Wxi, Wxg, Wxo,
                                              Whf, Whi, Whg, Who,
                                              bxf, bxi, bxg, bxo,
                                              bhf, bhi, bhg, bho);
    init_kernel<<<(2 * NGRP * NB * HH + 255) / 256, 256>>>();

    dim3 g1(GG / 128, TT);
    xproj_kernel<<<g1, 256, xp_smem>>>(x);

    lstm_kernel<<<NGRP * GCTA, 256, lstm_smem>>>((float*)d_out);
}

// round 6
// speedup vs baseline: 1.8171x; 1.0999x over previous
#include <cuda_runtime.h>
#include <cuda_bf16.h>
#include <cstdint>
#include <cstddef>

// Problem constants
#define BB   64          // batch
#define TT   1024        // timesteps
#define DD   512         // input dim
#define HH   512         // hidden dim
#define GG   2048        // 4*H gate dim
#define NGRP 4           // independent batch groups
#define GCTA 32          // CTAs per group
#define NB   16          // batches per group
#define NCOL 16          // hidden cols per CTA

// ---------------- device scratch ----------------
__device__ float    g_xproj[(size_t)TT * GG * BB];  // [t][gcol][b]
__device__ float    g_Wx[GG * DD];
__device__ float    g_Wh[GG * HH];
__device__ float    g_bsum[GG];
__device__ float    g_h[2][NGRP * NB * HH];         // per-group h, k-PERMUTED cols
__device__ unsigned g_bar4[NGRP * 32];              // padded barrier counters

// ---------------- helpers ----------------
__device__ __forceinline__ float tf32r(float x) {
    float y; asm("cvt.rna.tf32.f32 %0, %1;" : "=f"(y) : "f"(x)); return y;
}
__device__ __forceinline__ float tanh_fast(float x) {
    float y; asm("tanh.approx.f32 %0, %1;" : "=f"(y) : "f"(x)); return y;
}
__device__ __forceinline__ float sig_fast(float x) {
    return fmaf(tanh_fast(0.5f * x), 0.5f, 0.5f);
}
__device__ __forceinline__ void mma8(float* c,
                                     unsigned a0, unsigned a1, unsigned a2, unsigned a3,
                                     unsigned b0, unsigned b1) {
    asm volatile(
        "mma.sync.aligned.m16n8k8.row.col.f32.tf32.tf32.f32 "
        "{%0,%1,%2,%3},{%4,%5,%6,%7},{%8,%9},{%0,%1,%2,%3};\n"
        : "+f"(c[0]), "+f"(c[1]), "+f"(c[2]), "+f"(c[3])
        : "r"(a0), "r"(a1), "r"(a2), "r"(a3), "r"(b0), "r"(b1));
}
__device__ __forceinline__ void cp16(float* dst, const float* src) {
    unsigned s = (unsigned)__cvta_generic_to_shared(dst);
    asm volatile("cp.async.cg.shared.global [%0], [%1], 16;\n" :: "r"(s), "l"(src));
}
#define CP_COMMIT  asm volatile("cp.async.commit_group;\n" ::: "memory")
#define CP_WAIT(N) asm volatile("cp.async.wait_group %0;\n" :: "n"(N) : "memory")

// k-permutation within each 8-block: true offset o -> stored offset
__device__ __host__ __forceinline__ int kperm(int o) {
    return (o < 4) ? 2 * o : 2 * (o - 4) + 1;
}

// ---------------- pack kernel ----------------
__global__ void pack_kernel(
    const float* __restrict__ Wxf, const float* __restrict__ Wxi,
    const float* __restrict__ Wxg, const float* __restrict__ Wxo,
    const float* __restrict__ Whf, const float* __restrict__ Whi,
    const float* __restrict__ Whg, const float* __restrict__ Who,
    const float* __restrict__ bxf, const float* __restrict__ bxi,
    const float* __restrict__ bxg, const float* __restrict__ bxo,
    const float* __restrict__ bhf, const float* __restrict__ bhi,
    const float* __restrict__ bhg, const float* __restrict__ bho) {
    int i = blockIdx.x * blockDim.x + threadIdx.x;
    const float* WX[4] = {Wxf, Wxi, Wxg, Wxo};
    const float* WH[4] = {Whf, Whi, Whg, Who};
    const float* BX[4] = {bxf, bxi, bxg, bxo};
    const float* BH[4] = {bhf, bhi, bhg, bho};
    const int WN = GG * DD;
    if (i < WN) {
        int row = i >> 9, col = i & 511;
        int g = row >> 9, rr = row & 511;
        g_Wx[i] = tf32r(WX[g][rr * DD + col]);
    } else if (i < 2 * WN) {
        int j = i - WN;
        int row = j >> 9, col = j & 511;
        int g = row >> 9, rr = row & 511;
        g_Wh[j] = tf32r(WH[g][rr * HH + col]);
    } else if (i < 2 * WN + GG) {
        int j = i - 2 * WN;
        int g = j >> 9, rr = j & 511;
        g_bsum[j] = BX[g][rr] + BH[g][rr];
    }
}

__global__ void init_kernel() {
    int i = blockIdx.x * blockDim.x + threadIdx.x;
    if (i < 2 * NGRP * NB * HH) ((float*)g_h)[i] = 0.0f;
    if (i < NGRP * 32) g_bar4[i] = 0u;
}

// ---------------- phase 1: x_proj v2 (time-blocked) ----------------
// CTA tile: M = 128 gate cols, N = 256 (4 timesteps x 64 batches), K = 512.
// grid = (16 gate-tiles [fast], 256 t-blocks). 256 threads, 8 warps (4m x 2n).
// Warp tile m32 x n128. smem: A 2x[128][68], B 2x[256][68] = 204KB.
#define XP_SMEM_FLOATS (2 * 128 * 68 + 2 * 256 * 68)

__global__ void __launch_bounds__(256, 1) xproj_kernel(const float* __restrict__ x) {
    extern __shared__ float sm[];
    float* sA = sm;                   // [2][128][68]
    float* sB = sm + 2 * 128 * 68;    // [2][256][68]
    const int c0 = blockIdx.x * 128;
    const int t0 = blockIdx.y * 4;
    const int tid = threadIdx.x;
    const int w = tid >> 5, lane = tid & 31;
    const int wm = w & 3, wn = w >> 2;
    const int lg = lane >> 2, lt = lane & 3;

    float acc[2][16][4];
#pragma unroll
    for (int i = 0; i < 2; i++)
#pragma unroll
        for (int j = 0; j < 16; j++)
#pragma unroll
            for (int k = 0; k < 4; k++) acc[i][j][k] = 0.0f;

    auto loadA = [&](int buf, int k0) {
        float* dst = sA + buf * (128 * 68);
#pragma unroll
        for (int j = 0; j < 8; j++) {
            int l = tid + 256 * j;
            int row = l >> 4, q = l & 15;
            cp16(dst + row * 68 + q * 4, g_Wx + (size_t)(c0 + row) * DD + k0 + q * 4);
        }
    };
    auto loadB = [&](int buf, int k0) {
        float* dst = sB + buf * (256 * 68);
#pragma unroll
        for (int j = 0; j < 16; j++) {
            int l = tid + 256 * j;
            int row = l >> 4, q = l & 15;     // row = n = t'*64 + b
            int b = row & 63, tp = row >> 6;
            cp16(dst + row * 68 + q * 4,
                 x + ((size_t)b * TT + (t0 + tp)) * DD + k0 + q * 4);
        }
    };

    loadA(0, 0); loadB(0, 0); CP_COMMIT;
    for (int ch = 0; ch < 8; ch++) {
        if (ch < 7) {
            loadA((ch + 1) & 1, (ch + 1) * 64);
            loadB((ch + 1) & 1, (ch + 1) * 64);
            CP_COMMIT;
            CP_WAIT(1);
        } else {
            CP_WAIT(0);
        }
        __syncthreads();
        const float* A  = sA + (ch & 1) * (128 * 68);
        const float* Bm = sB + (ch & 1) * (256 * 68);
#pragma unroll
        for (int kk = 0; kk < 64; kk += 8) {
            unsigned a[2][4];
#pragma unroll
            for (int mi = 0; mi < 2; mi++) {
                const float* p = A + (wm * 32 + mi * 16 + lg) * 68 + kk + lt;
                a[mi][0] = __float_as_uint(p[0]);
                a[mi][1] = __float_as_uint(p[8 * 68]);
                a[mi][2] = __float_as_uint(p[4]);
                a[mi][3] = __float_as_uint(p[8 * 68 + 4]);
            }
#pragma unroll
            for (int ni = 0; ni < 16; ni++) {
                const float* p = Bm + (wn * 128 + ni * 8 + lg) * 68 + kk + lt;
                unsigned b0 = __float_as_uint(tf32r(p[0]));
                unsigned b1 = __float_as_uint(tf32r(p[4]));
                mma8(acc[0][ni], a[0][0], a[0][1], a[0][2], a[0][3], b0, b1);
                mma8(acc[1][ni], a[1][0], a[1][1], a[1][2], a[1][3], b0, b1);
            }
        }
        __syncthreads();
    }

    // epilogue: add (bx+bh), store [t][gcol][b]
#pragma unroll
    for (int mi = 0; mi < 2; mi++) {
#pragma unroll
        for (int rr = 0; rr < 2; rr++) {
            int gcol = c0 + wm * 32 + mi * 16 + rr * 8 + lg;
            float bs = g_bsum[gcol];
#pragma unroll
            for (int ni = 0; ni < 16; ni++) {
                int n = wn * 128 + ni * 8 + 2 * lt;
                int b = n & 63, tp = n >> 6;
                float2 v = make_float2(acc[mi][ni][2 * rr + 0] + bs,
                                       acc[mi][ni][2 * rr + 1] + bs);
                *(float2*)&g_xproj[(((size_t)(t0 + tp)) * GG + gcol) * BB + b] = v;
            }
        }
    }
}

// ---------------- phase 2: persistent recurrent kernel ----------------
// 128 CTAs x 256 threads. group = bid>>5 (16 batches), r = bid&31 (16 hidden cols).
// Per CTA: M = 64 gate rows, N = 16 batches, K = 512.
// ALL 8 warps mma: warp = (kh = w&1 K-half, gt = w>>1 gate-tile m16).
// K-halves merged in the cell update via sG[2][64][18].
#define SWHP_F4   (4 * 64 * 32)
#define SH_STRIDE 520
#define SG_STRIDE 18
#define LSTM_SMEM_BYTES ((SWHP_F4 * 4 + NB * SH_STRIDE + 2 * 64 * SG_STRIDE) * 4)

__global__ void __launch_bounds__(256, 1) lstm_kernel(float* __restrict__ out) {
    extern __shared__ float sm[];
    float4* sWhp = (float4*)sm;                       // A fragments [4 gt][64 q][32 lane]
    float*  sH   = sm + SWHP_F4 * 4;                  // [16][520] (k-permuted cols)
    float*  sG   = sH + NB * SH_STRIDE;               // [2][64][18]
    const int group = blockIdx.x >> 5;
    const int r     = blockIdx.x & 31;
    const int tid = threadIdx.x;
    const int w = tid >> 5, lane = tid & 31;
    const int lg = lane >> 2, lt = lane & 3;

    // ---- build pre-swizzled A fragments from g_Wh ----
    for (int i = tid; i < SWHP_F4; i += 256) {
        int gt = i >> 11;
        int rem = i & 2047;
        int q = rem >> 5, ln = rem & 31;
        int flg = ln >> 2, flt = ln & 3;
        int row0 = gt * 512 + r * NCOL + flg;
        int row1 = row0 + 8;
        int c0 = q * 8 + flt, c1 = c0 + 4;
        float4 v;
        v.x = g_Wh[(size_t)row0 * HH + c0];
        v.y = g_Wh[(size_t)row1 * HH + c0];
        v.z = g_Wh[(size_t)row0 * HH + c1];
        v.w = g_Wh[(size_t)row1 * HH + c1];
        sWhp[i] = v;
    }

    // cell-update ownership: 1 cell per thread
    const int jl = tid >> 4;          // local hidden col 0..15
    const int bl = tid & 15;          // local batch 0..15
    const int jglob = r * NCOL + jl;
    const int bglob = group * NB + bl;
    const int pj = (jglob & ~7) | kperm(jglob & 7);
    float cst = 0.0f;

    float4 xc, xn;
    auto ldxp = [&](int tt) {
        const float* base = g_xproj + (size_t)tt * GG * BB;
        float4 v;
        v.x = base[(size_t)(0 * 512 + jglob) * BB + bglob];
        v.y = base[(size_t)(1 * 512 + jglob) * BB + bglob];
        v.z = base[(size_t)(2 * 512 + jglob) * BB + bglob];
        v.w = base[(size_t)(3 * 512 + jglob) * BB + bglob];
        return v;
    };
    xc = ldxp(0);
    __syncthreads();

    const int kh = w & 1;             // K-half
    const int gt = w >> 1;            // gate-tile (m16)
    const float4* aP = sWhp + gt * 2048 + lane;
    const float* bP0 = sH + (0 * 8 + lg) * SH_STRIDE + 2 * lt;
    const float* bP1 = sH + (1 * 8 + lg) * SH_STRIDE + 2 * lt;
    const int khoff = kh * 64 * SG_STRIDE;
    unsigned* mybar = &g_bar4[group * 32];

    for (int t = 0; t < TT; t++) {
        const float* hsrc = g_h[t & 1] + (size_t)group * NB * HH;
        float*       hdst = g_h[(t & 1) ^ 1] + (size_t)group * NB * HH;

        // stage h (16 x 512 f32, k-permuted layout preserved)
#pragma unroll
        for (int j = 0; j < 8; j++) {
            int l = tid + 256 * j;
            int row = l >> 7, q = l & 127;
            cp16(sH + row * SH_STRIDE + q * 4, hsrc + (size_t)row * HH + q * 4);
        }
        CP_COMMIT;

        if (t + 1 < TT) xn = ldxp(t + 1);

        CP_WAIT(0);
        __syncthreads();

        // all 8 warps: m16 x n16 over this warp's K-half (32 k-steps)
        {
            float acc[2][4];
#pragma unroll
            for (int a = 0; a < 2; a++)
#pragma unroll
                for (int d = 0; d < 4; d++) acc[a][d] = 0.0f;

#pragma unroll 8
            for (int q = 0; q < 32; q++) {
                int kq = kh * 32 + q;
                float4 av = aP[kq * 32];
                float2 b0 = *(const float2*)(bP0 + kq * 8);
                float2 b1 = *(const float2*)(bP1 + kq * 8);
                mma8(acc[0], __float_as_uint(av.x), __float_as_uint(av.y),
                     __float_as_uint(av.z), __float_as_uint(av.w),
                     __float_as_uint(b0.x), __float_as_uint(b0.y));
                mma8(acc[1], __float_as_uint(av.x), __float_as_uint(av.y),
                     __float_as_uint(av.z), __float_as_uint(av.w),
                     __float_as_uint(b1.x), __float_as_uint(b1.y));
            }

            // dump to sG[kh][gt*16 + row][batch]
#pragma unroll
            for (int nt = 0; nt < 2; nt++) {
                int nb0 = nt * 8 + 2 * lt;
                *(float2*)&sG[khoff + (gt * 16 + lg) * SG_STRIDE + nb0] =
                    make_float2(acc[nt][0], acc[nt][1]);
                *(float2*)&sG[khoff + (gt * 16 + lg + 8) * SG_STRIDE + nb0] =
                    make_float2(acc[nt][2], acc[nt][3]);
            }
        }
        __syncthreads();

        // cell update (1 cell per thread): merge K-halves
        {
            const int H2 = 64 * SG_STRIDE;
            float fv = sG[(0 * 16 + jl) * SG_STRIDE + bl] + sG[H2 + (0 * 16 + jl) * SG_STRIDE + bl] + xc.x;
            float iv = sG[(1 * 16 + jl) * SG_STRIDE + bl] + sG[H2 + (1 * 16 + jl) * SG_STRIDE + bl] + xc.y;
            float gv = sG[(2 * 16 + jl) * SG_STRIDE + bl] + sG[H2 + (2 * 16 + jl) * SG_STRIDE + bl] + xc.z;
            float ov = sG[(3 * 16 + jl) * SG_STRIDE + bl] + sG[H2 + (3 * 16 + jl) * SG_STRIDE + bl] + xc.w;
            float f_ = sig_fast(fv);
            float i_ = sig_fast(iv);
            float g_ = tanh_fast(gv);
            float o_ = sig_fast(ov);
            cst = f_ * cst + i_ * g_;
            float h_ = o_ * tanh_fast(cst);
            hdst[(size_t)bl * HH + pj] = tf32r(h_);
            if (t == TT - 1) out[(size_t)bglob * HH + jglob] = h_;
            xc = xn;
        }

        // group barrier
        __syncthreads();
        if (tid == 0) {
            unsigned one = 1u;
            asm volatile("red.release.gpu.global.add.u32 [%0], %1;"
                         :: "l"(mybar), "r"(one) : "memory");
            unsigned target = (unsigned)(t + 1) * GCTA;
            unsigned v;
            do {
                asm volatile("ld.acquire.gpu.global.u32 %0, [%1];"
                             : "=r"(v) : "l"(mybar) : "memory");
            } while (v < target);
        }
        __syncthreads();
    }
}

// ---------------- launcher ----------------
extern "C" void kernel_launch(void* const* d_in, const int* in_sizes, int n_in,
                              void* d_out, int out_size) {
    const float* x   = (const float*)d_in[0];
    const float* Whf = (const float*)d_in[1];  const float* bhf = (const float*)d_in[2];
    const float* Wxf = (const float*)d_in[3];  const float* bxf = (const float*)d_in[4];
    const float* Whi = (const float*)d_in[5];  const float* bhi = (const float*)d_in[6];
    const float* Wxi = (const float*)d_in[7];  const float* bxi = (const float*)d_in[8];
    const float* Whg = (const float*)d_in[9];  const float* bhg = (const float*)d_in[10];
    const float* Wxg = (const float*)d_in[11]; const float* bxg = (const float*)d_in[12];
    const float* Who = (const float*)d_in[13]; const float* bho = (const float*)d_in[14];
    const float* Wxo = (const float*)d_in[15]; const float* bxo = (const float*)d_in[16];

    const int xp_smem   = XP_SMEM_FLOATS * 4;    // 208896 B
    const int lstm_smem = LSTM_SMEM_BYTES;
    cudaFuncSetAttribute(xproj_kernel, cudaFuncAttributeMaxDynamicSharedMemorySize, xp_smem);
    cudaFuncSetAttribute(lstm_kernel,  cudaFuncAttributeMaxDynamicSharedMemorySize, lstm_smem);

    int packN = 2 * GG * DD + GG;
    pack_kernel<<<(packN + 255) / 256, 256>>>(Wxf, Wxi, Wxg, Wxo,
                                              Whf, Whi, Whg, Who,
                                              bxf, bxi, bxg, bxo,
                                              bhf, bhi, bhg, bho);
    init_kernel<<<(2 * NGRP * NB * HH + 255) / 256, 256>>>();

    dim3 g1(GG / 128, TT / 4);   // gate-tile fast for x L2 reuse
    xproj_kernel<<<g1, 256, xp_smem>>>(x);

    lstm_kernel<<<NGRP * GCTA, 256, lstm_smem>>>((float*)d_out);
}